// round 1
// baseline (speedup 1.0000x reference)
#include <cuda_runtime.h>
#include <math.h>

#define SEQ   512
#define BATCH 64
#define INDIM 1024
#define HDIM  1024
#define GDIM  4096   // 4*H

// Scratch: x_proj[m, g] with m = b*SEQ + s  (512 MB), and running cell state c.
__device__ float g_xproj[(size_t)SEQ * BATCH * GDIM];
__device__ float g_c[BATCH * HDIM];

// ---------------------------------------------------------------------------
// Kernel 1: x_proj = x @ W_ih^T + (b_ih + b_hh)
// A (32768 x 1024) row-major, W (4096 x 1024) row-major -> both K-contiguous.
// Tile: BM=128, BN=64, BK=16, 256 threads, 8x4 micro-tile per thread.
// ---------------------------------------------------------------------------
#define XBM 128
#define XBN 64
#define XBK 16

__global__ __launch_bounds__(256) void xproj_kernel(
    const float* __restrict__ A, const float* __restrict__ W,
    const float* __restrict__ b1, const float* __restrict__ b2)
{
    __shared__ float As[XBM][XBK + 1];
    __shared__ float Bs[XBN][XBK + 1];

    const int tid = threadIdx.x;
    const int tx = tid & 15;      // 0..15 -> 4 cols each
    const int ty = tid >> 4;      // 0..15 -> 8 rows each
    const int n0 = blockIdx.x * XBN;
    const int m0 = blockIdx.y * XBM;

    float acc[8][4];
#pragma unroll
    for (int i = 0; i < 8; i++)
#pragma unroll
        for (int j = 0; j < 4; j++) acc[i][j] = 0.f;

    for (int k0 = 0; k0 < INDIM; k0 += XBK) {
        // Load A tile: 128x16 floats = 512 float4, 2 per thread
#pragma unroll
        for (int l = 0; l < 2; l++) {
            int idx = tid + l * 256;
            int r = idx >> 2, kq = idx & 3;
            float4 v = *reinterpret_cast<const float4*>(
                A + (size_t)(m0 + r) * INDIM + k0 + kq * 4);
            As[r][kq * 4 + 0] = v.x; As[r][kq * 4 + 1] = v.y;
            As[r][kq * 4 + 2] = v.z; As[r][kq * 4 + 3] = v.w;
        }
        // Load W tile: 64x16 floats = 256 float4, 1 per thread
        {
            int r = tid >> 2, kq = tid & 3;
            float4 v = *reinterpret_cast<const float4*>(
                W + (size_t)(n0 + r) * INDIM + k0 + kq * 4);
            Bs[r][kq * 4 + 0] = v.x; Bs[r][kq * 4 + 1] = v.y;
            Bs[r][kq * 4 + 2] = v.z; Bs[r][kq * 4 + 3] = v.w;
        }
        __syncthreads();
#pragma unroll
        for (int kk = 0; kk < XBK; kk++) {
            float a[8], b[4];
#pragma unroll
            for (int i = 0; i < 8; i++) a[i] = As[ty * 8 + i][kk];
#pragma unroll
            for (int j = 0; j < 4; j++) b[j] = Bs[tx * 4 + j][kk];
#pragma unroll
            for (int i = 0; i < 8; i++)
#pragma unroll
                for (int j = 0; j < 4; j++) acc[i][j] += a[i] * b[j];
        }
        __syncthreads();
    }

    float bias[4];
#pragma unroll
    for (int j = 0; j < 4; j++) {
        int n = n0 + tx * 4 + j;
        bias[j] = b1[n] + b2[n];
    }
#pragma unroll
    for (int i = 0; i < 8; i++) {
        int m = m0 + ty * 8 + i;
        float4 v = make_float4(acc[i][0] + bias[0], acc[i][1] + bias[1],
                               acc[i][2] + bias[2], acc[i][3] + bias[3]);
        *reinterpret_cast<float4*>(g_xproj + (size_t)m * GDIM + n0 + tx * 4) = v;
    }
}

// ---------------------------------------------------------------------------
// Kernel 2: one LSTM timestep, fused gates-GEMM + pointwise.
// Each of 128 blocks owns 8 hidden columns j = [jt, jt+8) and computes gate
// columns {j, H+j, 2H+j, 3H+j} for all 64 batches (M=64, N=32, K=1024),
// then the elementwise LSTM update for those (b, j).
// h_{t-1} is read from the previous step's slice of the output buffer.
// ---------------------------------------------------------------------------
#define SBK 32

__device__ __forceinline__ float sigmoidf_(float x) {
    return 1.f / (1.f + expf(-x));
}

__global__ __launch_bounds__(256) void lstm_step_kernel(
    const float* __restrict__ h_src, int h_stride,
    const float* __restrict__ W_hh,
    float* __restrict__ out, int step)
{
    __shared__ float Hs[64][SBK + 1];   // reused as gate-exchange buffer
    __shared__ float Ws[32][SBK + 1];

    const int tid = threadIdx.x;
    const int tx = tid & 15;   // 0..15 -> 2 cols each
    const int ty = tid >> 4;   // 0..15 -> 4 rows each
    const int jt = blockIdx.x * 8;

    float acc[4][2];
#pragma unroll
    for (int i = 0; i < 4; i++) { acc[i][0] = 0.f; acc[i][1] = 0.f; }

    for (int k0 = 0; k0 < HDIM; k0 += SBK) {
        // Load h tile: 64x32 floats = 512 float4, 2 per thread
#pragma unroll
        for (int l = 0; l < 2; l++) {
            int idx = tid + l * 256;
            int b = idx >> 3, kq = idx & 7;
            float4 v = *reinterpret_cast<const float4*>(
                h_src + (size_t)b * h_stride + k0 + kq * 4);
            Hs[b][kq * 4 + 0] = v.x; Hs[b][kq * 4 + 1] = v.y;
            Hs[b][kq * 4 + 2] = v.z; Hs[b][kq * 4 + 3] = v.w;
        }
        // Load W_hh tile: 32 rows (4 gate groups x 8 cols) x 32 k = 256 float4
        {
            int r = tid >> 3, kq = tid & 7;
            int grow = (r >> 3) * HDIM + jt + (r & 7);
            float4 v = *reinterpret_cast<const float4*>(
                W_hh + (size_t)grow * HDIM + k0 + kq * 4);
            Ws[r][kq * 4 + 0] = v.x; Ws[r][kq * 4 + 1] = v.y;
            Ws[r][kq * 4 + 2] = v.z; Ws[r][kq * 4 + 3] = v.w;
        }
        __syncthreads();
#pragma unroll
        for (int kk = 0; kk < SBK; kk++) {
            float a[4], w[2];
#pragma unroll
            for (int i = 0; i < 4; i++) a[i] = Hs[ty * 4 + i][kk];
#pragma unroll
            for (int j = 0; j < 2; j++) w[j] = Ws[tx * 2 + j][kk];
#pragma unroll
            for (int i = 0; i < 4; i++)
#pragma unroll
                for (int j = 0; j < 2; j++) acc[i][j] += a[i] * w[j];
        }
        __syncthreads();
    }

    // Exchange gates through smem (reuse Hs: 64 x 33 floats, exactly fits)
    float* gsm = &Hs[0][0];
#pragma unroll
    for (int i = 0; i < 4; i++) {
        int b = ty * 4 + i;
#pragma unroll
        for (int j = 0; j < 2; j++) {
            int c = tx * 2 + j;                       // 0..31
            int gcol = (c >> 3) * HDIM + jt + (c & 7);
            float xp = g_xproj[((size_t)b * SEQ + step) * GDIM + gcol];
            gsm[b * 33 + c] = acc[i][j] + xp;
        }
    }
    __syncthreads();

    // Pointwise LSTM update: 64 batches x 8 js = 512 elements, 2 per thread
#pragma unroll
    for (int l = 0; l < 2; l++) {
        int pid = tid + l * 256;
        int b = pid >> 3, jj = pid & 7;
        float ig = gsm[b * 33 + jj];
        float fg = gsm[b * 33 + 8 + jj];
        float gg = gsm[b * 33 + 16 + jj];
        float og = gsm[b * 33 + 24 + jj];
        int j = jt + jj;
        float cold = g_c[b * HDIM + j];
        float cn = sigmoidf_(fg) * cold + sigmoidf_(ig) * tanhf(gg);
        float h = sigmoidf_(og) * tanhf(cn);
        g_c[b * HDIM + j] = cn;
        out[(size_t)b * SEQ * HDIM + (size_t)step * HDIM + j] = h;
    }
}

// ---------------------------------------------------------------------------
// Helpers
// ---------------------------------------------------------------------------
__global__ void init_c_kernel(const float* __restrict__ c0) {
    int i = blockIdx.x * blockDim.x + threadIdx.x;
    g_c[i] = c0[i];
}

__global__ void finalize_kernel(const float* __restrict__ out,
                                float* __restrict__ tail) {
    int i = blockIdx.x * blockDim.x + threadIdx.x;   // 0..65535
    int b = i >> 10, j = i & 1023;
    tail[i] = out[(size_t)b * SEQ * HDIM + (size_t)(SEQ - 1) * HDIM + j];
    tail[BATCH * HDIM + i] = g_c[i];
}

// ---------------------------------------------------------------------------
// Launch
// ---------------------------------------------------------------------------
extern "C" void kernel_launch(void* const* d_in, const int* in_sizes, int n_in,
                              void* d_out, int out_size) {
    const float* inp  = (const float*)d_in[0];
    const float* h0   = (const float*)d_in[1];
    const float* c0   = (const float*)d_in[2];
    const float* W_ih = (const float*)d_in[3];
    const float* W_hh = (const float*)d_in[4];
    const float* b_ih = (const float*)d_in[5];
    const float* b_hh = (const float*)d_in[6];
    float* out = (float*)d_out;

    // Input projection GEMM: grid (4096/64, 32768/128)
    dim3 gx(GDIM / XBN, (SEQ * BATCH) / XBM);
    xproj_kernel<<<gx, 256>>>(inp, W_ih, b_ih, b_hh);

    init_c_kernel<<<64, 1024>>>(c0);

    for (int t = 0; t < SEQ; t++) {
        const float* h_src = (t == 0) ? h0 : (out + (size_t)(t - 1) * HDIM);
        int h_stride = (t == 0) ? HDIM : SEQ * HDIM;
        lstm_step_kernel<<<128, 256>>>(h_src, h_stride, W_hh, out, t);
    }

    // Final (h, c) appended after the (S,B,H) output, if the harness expects them
    if (out_size >= SEQ * BATCH * HDIM + 2 * BATCH * HDIM) {
        finalize_kernel<<<64, 1024>>>(out, out + (size_t)SEQ * BATCH * HDIM);
    }
}